// round 16
// baseline (speedup 1.0000x reference)
#include <cuda_runtime.h>

#define N_NODES 20000
#define N_EDGES 320000
#define F_IN 6
#define HID 128
#define N_CLS 21
#define N_LAYERS 4
#define NUM_G 16
#define ZDIM 272

// ------------------------- scratch (static device globals) -------------------
__device__ float g_h[N_NODES * HID];            // node features
__device__ float g_proj[2][N_NODES * HID];      // Af (dst,f), Ad (dst,s)
__device__ float g_pair[N_NODES * HID * 2];     // interleaved (Bf, Bd) per [node][ch]
__device__ float g_agg[N_NODES * HID];          // aggregated messages
__device__ __align__(16) float g_es[N_EDGES * NUM_G];  // RBF rows (fp32), dst-sorted
__device__ int   g_srcs[N_EDGES];               // src node in dst-sorted order
__device__ int   g_cnt[N_NODES];
__device__ int   g_rowptr[N_NODES + 1];
__device__ int   g_cursor[N_NODES];
__device__ float g_sum[HID], g_sq[HID];

// ------------------------- helpers ------------------------------------------
__device__ __forceinline__ float warp_sum(float v) {
#pragma unroll
    for (int o = 16; o; o >>= 1) v += __shfl_xor_sync(0xffffffffu, v, o);
    return v;
}
__device__ __forceinline__ float sigm(float z) {
    return __fdividef(1.0f, 1.0f + __expf(-z));
}
__device__ __forceinline__ float softp(float z) {
    return fmaxf(z, 0.0f) + __logf(1.0f + __expf(-fabsf(z)));
}

// ------------------------- setup: zero counts + node embedding ---------------
__global__ void setup_kernel(const float* __restrict__ x,
                             const float* __restrict__ W,
                             const float* __restrict__ b) {
    int idx = blockIdx.x * blockDim.x + threadIdx.x;
    if (idx < N_NODES) g_cnt[idx] = 0;
    if (idx < N_NODES * HID) {
        int n = idx >> 7, c = idx & 127;
        float acc = b[c];
#pragma unroll
        for (int k = 0; k < F_IN; k++)
            acc = fmaf(x[n * F_IN + k], W[k * HID + c], acc);
        g_h[idx] = acc;
    }
}

__global__ void count_kernel(const int* __restrict__ ei) {
    int e = blockIdx.x * blockDim.x + threadIdx.x;
    if (e < N_EDGES) atomicAdd(&g_cnt[ei[N_EDGES + e]], 1);
}

// single-block exclusive scan of g_cnt -> g_rowptr (+ cursor copy)
__global__ void scan_kernel() {
    __shared__ int warp_sums[32];
    __shared__ int s_carry;
    int tid = threadIdx.x, lane = tid & 31, wid = tid >> 5;
    if (tid == 0) s_carry = 0;
    __syncthreads();
    for (int base = 0; base < N_NODES; base += 1024) {
        int i = base + tid;
        int v = (i < N_NODES) ? g_cnt[i] : 0;
        int x = v;
#pragma unroll
        for (int off = 1; off < 32; off <<= 1) {
            int y = __shfl_up_sync(0xffffffffu, x, off);
            if (lane >= off) x += y;
        }
        if (lane == 31) warp_sums[wid] = x;
        __syncthreads();
        if (wid == 0) {
            int s = warp_sums[lane];
#pragma unroll
            for (int off = 1; off < 32; off <<= 1) {
                int y = __shfl_up_sync(0xffffffffu, s, off);
                if (lane >= off) s += y;
            }
            warp_sums[lane] = s;
        }
        __syncthreads();
        int woff = (wid > 0) ? warp_sums[wid - 1] : 0;
        int incl = x + woff;
        if (i < N_NODES) {
            int ex = s_carry + incl - v;
            g_rowptr[i] = ex;
            g_cursor[i] = ex;
        }
        __syncthreads();
        if (tid == 0) s_carry += warp_sums[31];
        __syncthreads();
    }
    if (threadIdx.x == 0) g_rowptr[N_NODES] = s_carry;
}

// RBF expansion (fp32) + scatter into dst-sorted order
__global__ void rbf_scatter_kernel(const float* __restrict__ dist,
                                   const int* __restrict__ ei) {
    int e = blockIdx.x * blockDim.x + threadIdx.x;
    if (e >= N_EDGES) return;
    float d = dist[e];
    float ev[NUM_G];
#pragma unroll
    for (int k = 0; k < NUM_G; k++) {
        float t = d - (float)k * (8.0f / 15.0f);
        ev[k] = __expf(-1.7578125f * t * t);
    }
    int dst = ei[N_EDGES + e];
    int src = ei[e];
    int p = atomicAdd(&g_cursor[dst], 1);
    g_srcs[p] = src;
    float* o = &g_es[p * NUM_G];
    *(float4*)&o[0]  = make_float4(ev[0], ev[1], ev[2], ev[3]);
    *(float4*)&o[4]  = make_float4(ev[4], ev[5], ev[6], ev[7]);
    *(float4*)&o[8]  = make_float4(ev[8], ev[9], ev[10], ev[11]);
    *(float4*)&o[12] = make_float4(ev[12], ev[13], ev[14], ev[15]);
}

// ------------------------- per-layer node GEMM (128x128, BK=16, dbuf) --------
// nb: 0 -> Af (g_proj[0]), 1 -> Bf (g_pair even), 2 -> Ad (g_proj[1]), 3 -> Bd (g_pair odd)
__global__ __launch_bounds__(256, 2) void gemm_node_kernel(
    const float* __restrict__ Wf, const float* __restrict__ Ws, int layer) {
    if (blockIdx.x == 0 && blockIdx.y == 0 && threadIdx.x < HID) {
        g_sum[threadIdx.x] = 0.0f;
        g_sq[threadIdx.x] = 0.0f;
    }

    int nb = blockIdx.y;
    const float* B = ((nb < 2) ? Wf : Ws) + layer * ZDIM * HID + (nb & 1) * HID * HID;
    int m0 = blockIdx.x * 128;

    __shared__ float As[2][16][132];
    __shared__ float Bs[2][16][128];

    int tid = threadIdx.x;
    int tx = tid & 15, ty = tid >> 4;

    int arow = tid & 127;
    int akq = (tid >> 7) * 8;
    int brow = tid >> 4;
    int bcol = (tid & 15) * 8;

    float acc[8][8];
#pragma unroll
    for (int i = 0; i < 8; i++)
#pragma unroll
        for (int j = 0; j < 8; j++) acc[i][j] = 0.0f;

    int gm_a = m0 + arow;
    bool a_ok = (gm_a < N_NODES);
    const float* a_ptr = &g_h[(a_ok ? gm_a : 0) * HID + akq];

    float4 pa0 = make_float4(0.f, 0.f, 0.f, 0.f), pa1 = pa0;
    if (a_ok) { pa0 = *(const float4*)&a_ptr[0]; pa1 = *(const float4*)&a_ptr[4]; }
    float4 pb0 = *(const float4*)&B[brow * HID + bcol];
    float4 pb1 = *(const float4*)&B[brow * HID + bcol + 4];
    {
        As[0][akq + 0][arow] = pa0.x; As[0][akq + 1][arow] = pa0.y;
        As[0][akq + 2][arow] = pa0.z; As[0][akq + 3][arow] = pa0.w;
        As[0][akq + 4][arow] = pa1.x; As[0][akq + 5][arow] = pa1.y;
        As[0][akq + 6][arow] = pa1.z; As[0][akq + 7][arow] = pa1.w;
        *(float4*)&Bs[0][brow][bcol] = pb0;
        *(float4*)&Bs[0][brow][bcol + 4] = pb1;
    }
    __syncthreads();

#pragma unroll
    for (int s = 0; s < 8; s++) {
        int buf = s & 1;
        if (s < 7) {
            int k0 = (s + 1) * 16;
            pa0 = make_float4(0.f, 0.f, 0.f, 0.f); pa1 = pa0;
            if (a_ok) {
                pa0 = *(const float4*)&a_ptr[k0];
                pa1 = *(const float4*)&a_ptr[k0 + 4];
            }
            pb0 = *(const float4*)&B[(k0 + brow) * HID + bcol];
            pb1 = *(const float4*)&B[(k0 + brow) * HID + bcol + 4];
        }
#pragma unroll
        for (int k = 0; k < 16; k++) {
            float4 a0 = *(const float4*)&As[buf][k][ty * 4];
            float4 a1 = *(const float4*)&As[buf][k][64 + ty * 4];
            float4 b0 = *(const float4*)&Bs[buf][k][tx * 4];
            float4 b1 = *(const float4*)&Bs[buf][k][64 + tx * 4];
            float av[8] = {a0.x, a0.y, a0.z, a0.w, a1.x, a1.y, a1.z, a1.w};
            float bv[8] = {b0.x, b0.y, b0.z, b0.w, b1.x, b1.y, b1.z, b1.w};
#pragma unroll
            for (int i = 0; i < 8; i++)
#pragma unroll
                for (int j = 0; j < 8; j++)
                    acc[i][j] = fmaf(av[i], bv[j], acc[i][j]);
        }
        if (s < 7) {
            int nbuf = buf ^ 1;
            As[nbuf][akq + 0][arow] = pa0.x; As[nbuf][akq + 1][arow] = pa0.y;
            As[nbuf][akq + 2][arow] = pa0.z; As[nbuf][akq + 3][arow] = pa0.w;
            As[nbuf][akq + 4][arow] = pa1.x; As[nbuf][akq + 5][arow] = pa1.y;
            As[nbuf][akq + 6][arow] = pa1.z; As[nbuf][akq + 7][arow] = pa1.w;
            *(float4*)&Bs[nbuf][brow][bcol] = pb0;
            *(float4*)&Bs[nbuf][brow][bcol + 4] = pb1;
        }
        __syncthreads();
    }

    if (nb == 0 || nb == 2) {
        float* out = g_proj[nb >> 1];
#pragma unroll
        for (int i = 0; i < 4; i++) {
            int gm = m0 + ty * 4 + i;
            if (gm < N_NODES) {
                *(float4*)&out[gm * HID + tx * 4] =
                    make_float4(acc[i][0], acc[i][1], acc[i][2], acc[i][3]);
                *(float4*)&out[gm * HID + 64 + tx * 4] =
                    make_float4(acc[i][4], acc[i][5], acc[i][6], acc[i][7]);
            }
            int gm2 = m0 + 64 + ty * 4 + i;
            if (gm2 < N_NODES) {
                *(float4*)&out[gm2 * HID + tx * 4] =
                    make_float4(acc[4 + i][0], acc[4 + i][1], acc[4 + i][2], acc[4 + i][3]);
                *(float4*)&out[gm2 * HID + 64 + tx * 4] =
                    make_float4(acc[4 + i][4], acc[4 + i][5], acc[4 + i][6], acc[4 + i][7]);
            }
        }
    } else {
        float* op = g_pair + ((nb == 1) ? 0 : 1);
#pragma unroll
        for (int i = 0; i < 4; i++) {
            int gm = m0 + ty * 4 + i;
            if (gm < N_NODES) {
#pragma unroll
                for (int j = 0; j < 4; j++) {
                    op[(gm * HID + tx * 4 + j) * 2] = acc[i][j];
                    op[(gm * HID + 64 + tx * 4 + j) * 2] = acc[i][4 + j];
                }
            }
            int gm2 = m0 + 64 + ty * 4 + i;
            if (gm2 < N_NODES) {
#pragma unroll
                for (int j = 0; j < 4; j++) {
                    op[(gm2 * HID + tx * 4 + j) * 2] = acc[4 + i][j];
                    op[(gm2 * HID + 64 + tx * 4 + j) * 2] = acc[4 + i][4 + j];
                }
            }
        }
    }
}

// ------ edge aggregation: ONE node per 128-thread CTA.
//        Warp w: channels [(w>>1)*64, +64) at 2 ch/lane; edge parity (w&1).
//        fp32 e-rows with depth-1 e-prefetch + depth-2 gather pipeline.
__global__ __launch_bounds__(128) void edge_agg_kernel(
    const float* __restrict__ Wf, const float* __restrict__ Ws,
    const float* __restrict__ bfb, const float* __restrict__ bsb, int layer) {
    __shared__ float sred[2][HID];

    const float* Wfl = Wf + layer * ZDIM * HID + 256 * HID;   // RBF rows
    const float* Wsl = Ws + layer * ZDIM * HID + 256 * HID;

    int node = blockIdx.x;
    int tid = threadIdx.x, warp = tid >> 5, lane = tid & 31;
    int par = warp & 1;                      // edge parity
    int ch0 = (warp >> 1) * 64 + lane * 2;   // 2 consecutive channels

    // weights for 2 channels: float2 per gaussian
    float2 wf[NUM_G], ws[NUM_G];
#pragma unroll
    for (int k = 0; k < NUM_G; k++) {
        wf[k] = *(const float2*)&Wfl[k * HID + ch0];
        ws[k] = *(const float2*)&Wsl[k * HID + ch0];
    }

    // pair gather: (Bf[ch0],Bd[ch0],Bf[ch0+1],Bd[ch0+1]) = one float4
    const float4* PairC = ((const float4*)g_pair) + (ch0 >> 1);

    float af0 = g_proj[0][node * HID + ch0]     + bfb[layer * HID + ch0];
    float af1 = g_proj[0][node * HID + ch0 + 1] + bfb[layer * HID + ch0 + 1];
    float as0 = g_proj[1][node * HID + ch0]     + bsb[layer * HID + ch0];
    float as1 = g_proj[1][node * HID + ch0 + 1] + bsb[layer * HID + ch0 + 1];

    int start = g_rowptr[node], end = g_rowptr[node + 1];
    float acc0 = 0.0f, acc1 = 0.0f;

    int i0 = start + par;
    if (i0 < end) {
        // prime: gathers for edges i0 and i0+2 in flight; e-row for i0 loaded.
        // Clamps use the global bound — out-of-range slots hold other nodes'
        // valid src ids / e-rows; their values are never consumed.
        int s0 = g_srcs[i0];
        int s1 = g_srcs[min(i0 + 2, N_EDGES - 1)];
        float4 p0 = PairC[s0 * 64];
        float4 p1 = PairC[s1 * 64];
        const float* ep0 = &g_es[i0 * NUM_G];
        float4 e0 = *(const float4*)&ep0[0];
        float4 e1 = *(const float4*)&ep0[4];
        float4 e2 = *(const float4*)&ep0[8];
        float4 e3 = *(const float4*)&ep0[12];

        for (int i = i0; i < end; i += 2) {
            // prefetch gather for edge i+4
            int s2 = g_srcs[min(i + 4, N_EDGES - 1)];
            float4 pn = PairC[s2 * 64];
            // prefetch e-row for edge i+2 (consumed next iteration)
            const float* np = &g_es[min(i + 2, N_EDGES - 1) * NUM_G];
            float4 n0 = *(const float4*)&np[0];
            float4 n1 = *(const float4*)&np[4];
            float4 n2 = *(const float4*)&np[8];
            float4 n3 = *(const float4*)&np[12];

            // compute edge i (e-row and gather both issued last iteration)
            float zf0 = af0 + p0.x, zs0 = as0 + p0.y;
            float zf1 = af1 + p0.z, zs1 = as1 + p0.w;
#define RBF1(ev, k)                                       \
            zf0 = fmaf(ev, wf[k].x, zf0);                 \
            zs0 = fmaf(ev, ws[k].x, zs0);                 \
            zf1 = fmaf(ev, wf[k].y, zf1);                 \
            zs1 = fmaf(ev, ws[k].y, zs1);
            RBF1(e0.x, 0)  RBF1(e0.y, 1)  RBF1(e0.z, 2)  RBF1(e0.w, 3)
            RBF1(e1.x, 4)  RBF1(e1.y, 5)  RBF1(e1.z, 6)  RBF1(e1.w, 7)
            RBF1(e2.x, 8)  RBF1(e2.y, 9)  RBF1(e2.z, 10) RBF1(e2.w, 11)
            RBF1(e3.x, 12) RBF1(e3.y, 13) RBF1(e3.z, 14) RBF1(e3.w, 15)
#undef RBF1
            acc0 += sigm(zf0) * softp(zs0);
            acc1 += sigm(zf1) * softp(zs1);

            // rotate pipelines
            p0 = p1; p1 = pn;
            e0 = n0; e1 = n1; e2 = n2; e3 = n3;
        }
    }

    // cross-parity reduction (one barrier per node)
    *(float2*)&sred[par][ch0] = make_float2(acc0, acc1);
    __syncthreads();
    {
        float a = sred[0][tid] + sred[1][tid];
        g_agg[node * HID + tid] = a;
        atomicAdd(&g_sum[tid], a);
        atomicAdd(&g_sq[tid], a * a);
    }
}

// ------------------------- BN + residual + LN + ReLU + residual --------------
__global__ __launch_bounds__(256) void bn_ln_kernel(
    const float* __restrict__ bn_g, const float* __restrict__ bn_b,
    const float* __restrict__ ln_g, const float* __restrict__ ln_b, int layer) {
    __shared__ __align__(16) float sA[HID];
    __shared__ __align__(16) float sB[HID];
    int tid = threadIdx.x;
    if (tid < HID) {
        const float inv = 1.0f / (float)N_NODES;
        float mu = g_sum[tid] * inv;
        float var = g_sq[tid] * inv - mu * mu;
        float rs = rsqrtf(var + 1e-5f);
        float a = rs * bn_g[layer * HID + tid];
        sA[tid] = a;
        sB[tid] = bn_b[layer * HID + tid] - mu * a;
    }
    __syncthreads();

    int warp = tid >> 5, lane = tid & 31;
    int node = blockIdx.x * 8 + warp;
    int ch0 = lane * 4;

    float4 ag = *(const float4*)&g_agg[node * HID + ch0];
    float4 h4 = *(const float4*)&g_h[node * HID + ch0];
    float4 a4 = *(const float4*)&sA[ch0];
    float4 b4 = *(const float4*)&sB[ch0];

    float c0 = fmaf(ag.x, a4.x, b4.x) + h4.x;
    float c1 = fmaf(ag.y, a4.y, b4.y) + h4.y;
    float c2 = fmaf(ag.z, a4.z, b4.z) + h4.z;
    float c3 = fmaf(ag.w, a4.w, b4.w) + h4.w;

    float s = warp_sum(c0 + c1 + c2 + c3);
    float mean = s * (1.0f / HID);
    float sq = warp_sum(c0 * c0 + c1 * c1 + c2 * c2 + c3 * c3);
    float var = sq * (1.0f / HID) - mean * mean;
    float rs = rsqrtf(var + 1e-5f);

    float4 lg = *(const float4*)&ln_g[layer * HID + ch0];
    float4 lb = *(const float4*)&ln_b[layer * HID + ch0];

    float r0 = fmaxf(fmaf((c0 - mean) * rs, lg.x, lb.x), 0.0f) + h4.x;
    float r1 = fmaxf(fmaf((c1 - mean) * rs, lg.y, lb.y), 0.0f) + h4.y;
    float r2 = fmaxf(fmaf((c2 - mean) * rs, lg.z, lb.z), 0.0f) + h4.z;
    float r3 = fmaxf(fmaf((c3 - mean) * rs, lg.w, lb.w), 0.0f) + h4.w;

    *(float4*)&g_h[node * HID + ch0] = make_float4(r0, r1, r2, r3);
}

// ------------------------- final LN + FC -------------------------------------
__global__ __launch_bounds__(256) void final_kernel(
    const float* __restrict__ lng, const float* __restrict__ lnb,
    const float* __restrict__ Wfc, const float* __restrict__ bfc,
    float* __restrict__ out) {
    int warp = threadIdx.x >> 5, lane = threadIdx.x & 31;
    int node = blockIdx.x * 8 + warp;
    int ch0 = lane * 4;

    float4 h4 = *(const float4*)&g_h[node * HID + ch0];
    float s = warp_sum(h4.x + h4.y + h4.z + h4.w);
    float mean = s * (1.0f / HID);
    float sq = warp_sum(h4.x * h4.x + h4.y * h4.y + h4.z * h4.z + h4.w * h4.w);
    float var = sq * (1.0f / HID) - mean * mean;
    float rs = rsqrtf(var + 1e-5f);

    float4 lg = *(const float4*)&lng[ch0];
    float4 lb = *(const float4*)&lnb[ch0];
    float hn0 = fmaf((h4.x - mean) * rs, lg.x, lb.x);
    float hn1 = fmaf((h4.y - mean) * rs, lg.y, lb.y);
    float hn2 = fmaf((h4.z - mean) * rs, lg.z, lb.z);
    float hn3 = fmaf((h4.w - mean) * rs, lg.w, lb.w);

#pragma unroll
    for (int j = 0; j < N_CLS; j++) {
        float p = hn0 * Wfc[(ch0 + 0) * N_CLS + j]
                + hn1 * Wfc[(ch0 + 1) * N_CLS + j]
                + hn2 * Wfc[(ch0 + 2) * N_CLS + j]
                + hn3 * Wfc[(ch0 + 3) * N_CLS + j];
        p = warp_sum(p);
        if (lane == 0) out[node * N_CLS + j] = p + bfc[j];
    }
}

// ------------------------- launch -------------------------------------------
extern "C" void kernel_launch(void* const* d_in, const int* in_sizes, int n_in,
                              void* d_out, int out_size) {
    const float* x        = (const float*)d_in[0];
    const int*   ei       = (const int*)d_in[1];
    const float* dist     = (const float*)d_in[2];
    const float* W_node   = (const float*)d_in[3];
    const float* b_node   = (const float*)d_in[4];
    const float* Wf       = (const float*)d_in[5];
    const float* bf       = (const float*)d_in[6];
    const float* Ws       = (const float*)d_in[7];
    const float* bs       = (const float*)d_in[8];
    const float* bn_g     = (const float*)d_in[9];
    const float* bn_b     = (const float*)d_in[10];
    const float* ln_g     = (const float*)d_in[11];
    const float* ln_b     = (const float*)d_in[12];
    const float* lnout_g  = (const float*)d_in[13];
    const float* lnout_b  = (const float*)d_in[14];
    const float* W_fc     = (const float*)d_in[15];
    const float* b_fc     = (const float*)d_in[16];
    float* out = (float*)d_out;

    setup_kernel<<<(N_NODES * HID + 255) / 256, 256>>>(x, W_node, b_node);   // 1
    count_kernel<<<(N_EDGES + 255) / 256, 256>>>(ei);                        // 2
    scan_kernel<<<1, 1024>>>();                                              // 3
    gemm_node_kernel<<<dim3(157, 4), 256>>>(Wf, Ws, 0);                      // 4
    rbf_scatter_kernel<<<(N_EDGES + 255) / 256, 256>>>(dist, ei);            // 5
    edge_agg_kernel<<<N_NODES, 128>>>(Wf, Ws, bf, bs, 0);                    // 6
    bn_ln_kernel<<<N_NODES / 8, 256>>>(bn_g, bn_b, ln_g, ln_b, 0);           // 7

    for (int l = 1; l < N_LAYERS; l++) {
        gemm_node_kernel<<<dim3(157, 4), 256>>>(Wf, Ws, l);
        edge_agg_kernel<<<N_NODES, 128>>>(Wf, Ws, bf, bs, l);
        bn_ln_kernel<<<N_NODES / 8, 256>>>(bn_g, bn_b, ln_g, ln_b, l);
    }

    final_kernel<<<N_NODES / 8, 256>>>(lnout_g, lnout_b, W_fc, b_fc, out);
}

// round 17
// speedup vs baseline: 1.0678x; 1.0678x over previous
#include <cuda_runtime.h>

#define N_NODES 20000
#define N_EDGES 320000
#define F_IN 6
#define HID 128
#define N_CLS 21
#define N_LAYERS 4
#define NUM_G 16
#define ZDIM 272

// ------------------------- scratch (static device globals) -------------------
__device__ float g_h[N_NODES * HID];            // node features
__device__ float g_proj[2][N_NODES * HID];      // Af (dst,f), Ad (dst,s)
__device__ float g_pair[N_NODES * HID * 2];     // interleaved (Bf, Bd) per [node][ch]
__device__ float g_agg[N_NODES * HID];          // aggregated messages
__device__ __align__(16) float g_es[N_EDGES * NUM_G];  // RBF rows (fp32), dst-sorted
__device__ int   g_srcs[N_EDGES];               // src node in dst-sorted order
__device__ int   g_cnt[N_NODES];
__device__ int   g_rowptr[N_NODES + 1];
__device__ int   g_cursor[N_NODES];
__device__ float g_sum[HID], g_sq[HID];

// ------------------------- helpers ------------------------------------------
__device__ __forceinline__ float warp_sum(float v) {
#pragma unroll
    for (int o = 16; o; o >>= 1) v += __shfl_xor_sync(0xffffffffu, v, o);
    return v;
}
__device__ __forceinline__ float sigm(float z) {
    return __fdividef(1.0f, 1.0f + __expf(-z));
}
__device__ __forceinline__ float softp(float z) {
    return fmaxf(z, 0.0f) + __logf(1.0f + __expf(-fabsf(z)));
}

// ------------------------- setup: zero counts + node embedding ---------------
__global__ void setup_kernel(const float* __restrict__ x,
                             const float* __restrict__ W,
                             const float* __restrict__ b) {
    int idx = blockIdx.x * blockDim.x + threadIdx.x;
    if (idx < N_NODES) g_cnt[idx] = 0;
    if (idx < N_NODES * HID) {
        int n = idx >> 7, c = idx & 127;
        float acc = b[c];
#pragma unroll
        for (int k = 0; k < F_IN; k++)
            acc = fmaf(x[n * F_IN + k], W[k * HID + c], acc);
        g_h[idx] = acc;
    }
}

__global__ void count_kernel(const int* __restrict__ ei) {
    int e = blockIdx.x * blockDim.x + threadIdx.x;
    if (e < N_EDGES) atomicAdd(&g_cnt[ei[N_EDGES + e]], 1);
}

// single-block exclusive scan of g_cnt -> g_rowptr (+ cursor copy)
__global__ void scan_kernel() {
    __shared__ int warp_sums[32];
    __shared__ int s_carry;
    int tid = threadIdx.x, lane = tid & 31, wid = tid >> 5;
    if (tid == 0) s_carry = 0;
    __syncthreads();
    for (int base = 0; base < N_NODES; base += 1024) {
        int i = base + tid;
        int v = (i < N_NODES) ? g_cnt[i] : 0;
        int x = v;
#pragma unroll
        for (int off = 1; off < 32; off <<= 1) {
            int y = __shfl_up_sync(0xffffffffu, x, off);
            if (lane >= off) x += y;
        }
        if (lane == 31) warp_sums[wid] = x;
        __syncthreads();
        if (wid == 0) {
            int s = warp_sums[lane];
#pragma unroll
            for (int off = 1; off < 32; off <<= 1) {
                int y = __shfl_up_sync(0xffffffffu, s, off);
                if (lane >= off) s += y;
            }
            warp_sums[lane] = s;
        }
        __syncthreads();
        int woff = (wid > 0) ? warp_sums[wid - 1] : 0;
        int incl = x + woff;
        if (i < N_NODES) {
            int ex = s_carry + incl - v;
            g_rowptr[i] = ex;
            g_cursor[i] = ex;
        }
        __syncthreads();
        if (tid == 0) s_carry += warp_sums[31];
        __syncthreads();
    }
    if (threadIdx.x == 0) g_rowptr[N_NODES] = s_carry;
}

// RBF expansion (fp32) + scatter into dst-sorted order
__global__ void rbf_scatter_kernel(const float* __restrict__ dist,
                                   const int* __restrict__ ei) {
    int e = blockIdx.x * blockDim.x + threadIdx.x;
    if (e >= N_EDGES) return;
    float d = dist[e];
    float ev[NUM_G];
#pragma unroll
    for (int k = 0; k < NUM_G; k++) {
        float t = d - (float)k * (8.0f / 15.0f);
        ev[k] = __expf(-1.7578125f * t * t);
    }
    int dst = ei[N_EDGES + e];
    int src = ei[e];
    int p = atomicAdd(&g_cursor[dst], 1);
    g_srcs[p] = src;
    float* o = &g_es[p * NUM_G];
    *(float4*)&o[0]  = make_float4(ev[0], ev[1], ev[2], ev[3]);
    *(float4*)&o[4]  = make_float4(ev[4], ev[5], ev[6], ev[7]);
    *(float4*)&o[8]  = make_float4(ev[8], ev[9], ev[10], ev[11]);
    *(float4*)&o[12] = make_float4(ev[12], ev[13], ev[14], ev[15]);
}

// ------------------- per-layer node GEMM (64x128 tile, BK=16, dbuf) ----------
// 3 CTAs/SM (wave-quantization fix). 256 thr, 4x8 microtile.
// nb: 0 -> Af (g_proj[0]), 1 -> Bf (g_pair even), 2 -> Ad (g_proj[1]), 3 -> Bd (g_pair odd)
__global__ __launch_bounds__(256, 3) void gemm_node_kernel(
    const float* __restrict__ Wf, const float* __restrict__ Ws, int layer) {
    if (blockIdx.x == 0 && blockIdx.y == 0 && threadIdx.x < HID) {
        g_sum[threadIdx.x] = 0.0f;
        g_sq[threadIdx.x] = 0.0f;
    }

    int nb = blockIdx.y;
    const float* B = ((nb < 2) ? Wf : Ws) + layer * ZDIM * HID + (nb & 1) * HID * HID;
    int m0 = blockIdx.x * 64;

    __shared__ float As[2][16][68];
    __shared__ float Bs[2][16][128];

    int tid = threadIdx.x;
    int tx = tid & 15, ty = tid >> 4;

    // A load mapping: 64 rows x 16 k = 256 float4; one per thread
    int arow = tid & 63;
    int akq = (tid >> 6) * 4;           // 4 k's per thread
    // B load mapping: 16 rows x 128 cols = 512 float4; two per thread
    int brow = tid >> 4;
    int bcol = (tid & 15) * 8;

    float acc[4][8];
#pragma unroll
    for (int i = 0; i < 4; i++)
#pragma unroll
        for (int j = 0; j < 8; j++) acc[i][j] = 0.0f;

    int gm_a = m0 + arow;
    bool a_ok = (gm_a < N_NODES);
    const float* a_ptr = &g_h[(a_ok ? gm_a : 0) * HID + akq];

    float4 pa = make_float4(0.f, 0.f, 0.f, 0.f);
    if (a_ok) pa = *(const float4*)&a_ptr[0];
    float4 pb0 = *(const float4*)&B[brow * HID + bcol];
    float4 pb1 = *(const float4*)&B[brow * HID + bcol + 4];
    {
        As[0][akq + 0][arow] = pa.x;
        As[0][akq + 1][arow] = pa.y;
        As[0][akq + 2][arow] = pa.z;
        As[0][akq + 3][arow] = pa.w;
        *(float4*)&Bs[0][brow][bcol] = pb0;
        *(float4*)&Bs[0][brow][bcol + 4] = pb1;
    }
    __syncthreads();

#pragma unroll
    for (int s = 0; s < 8; s++) {
        int buf = s & 1;
        if (s < 7) {
            int k0 = (s + 1) * 16;
            pa = make_float4(0.f, 0.f, 0.f, 0.f);
            if (a_ok) pa = *(const float4*)&a_ptr[k0];
            pb0 = *(const float4*)&B[(k0 + brow) * HID + bcol];
            pb1 = *(const float4*)&B[(k0 + brow) * HID + bcol + 4];
        }
#pragma unroll
        for (int k = 0; k < 16; k++) {
            float4 a0 = *(const float4*)&As[buf][k][ty * 4];
            float4 b0 = *(const float4*)&Bs[buf][k][tx * 4];
            float4 b1 = *(const float4*)&Bs[buf][k][64 + tx * 4];
            float av[4] = {a0.x, a0.y, a0.z, a0.w};
            float bv[8] = {b0.x, b0.y, b0.z, b0.w, b1.x, b1.y, b1.z, b1.w};
#pragma unroll
            for (int i = 0; i < 4; i++)
#pragma unroll
                for (int j = 0; j < 8; j++)
                    acc[i][j] = fmaf(av[i], bv[j], acc[i][j]);
        }
        if (s < 7) {
            int nbuf = buf ^ 1;
            As[nbuf][akq + 0][arow] = pa.x;
            As[nbuf][akq + 1][arow] = pa.y;
            As[nbuf][akq + 2][arow] = pa.z;
            As[nbuf][akq + 3][arow] = pa.w;
            *(float4*)&Bs[nbuf][brow][bcol] = pb0;
            *(float4*)&Bs[nbuf][brow][bcol + 4] = pb1;
        }
        __syncthreads();
    }

    if (nb == 0 || nb == 2) {
        float* out = g_proj[nb >> 1];
#pragma unroll
        for (int i = 0; i < 4; i++) {
            int gm = m0 + ty * 4 + i;
            if (gm < N_NODES) {
                *(float4*)&out[gm * HID + tx * 4] =
                    make_float4(acc[i][0], acc[i][1], acc[i][2], acc[i][3]);
                *(float4*)&out[gm * HID + 64 + tx * 4] =
                    make_float4(acc[i][4], acc[i][5], acc[i][6], acc[i][7]);
            }
        }
    } else {
        float* op = g_pair + ((nb == 1) ? 0 : 1);
#pragma unroll
        for (int i = 0; i < 4; i++) {
            int gm = m0 + ty * 4 + i;
            if (gm < N_NODES) {
#pragma unroll
                for (int j = 0; j < 4; j++) {
                    op[(gm * HID + tx * 4 + j) * 2] = acc[i][j];
                    op[(gm * HID + 64 + tx * 4 + j) * 2] = acc[i][4 + j];
                }
            }
        }
    }
}

// ------ edge aggregation: ONE node per 128-thread CTA.
//        Warp w: channels [(w>>1)*64, +64) at 2 ch/lane; edge parity (w&1).
//        fp32 e-rows with depth-1 e-prefetch + depth-2 gather pipeline.
__global__ __launch_bounds__(128) void edge_agg_kernel(
    const float* __restrict__ Wf, const float* __restrict__ Ws,
    const float* __restrict__ bfb, const float* __restrict__ bsb, int layer) {
    __shared__ float sred[2][HID];

    const float* Wfl = Wf + layer * ZDIM * HID + 256 * HID;   // RBF rows
    const float* Wsl = Ws + layer * ZDIM * HID + 256 * HID;

    int node = blockIdx.x;
    int tid = threadIdx.x, warp = tid >> 5, lane = tid & 31;
    int par = warp & 1;                      // edge parity
    int ch0 = (warp >> 1) * 64 + lane * 2;   // 2 consecutive channels

    // weights for 2 channels: float2 per gaussian
    float2 wf[NUM_G], ws[NUM_G];
#pragma unroll
    for (int k = 0; k < NUM_G; k++) {
        wf[k] = *(const float2*)&Wfl[k * HID + ch0];
        ws[k] = *(const float2*)&Wsl[k * HID + ch0];
    }

    // pair gather: (Bf[ch0],Bd[ch0],Bf[ch0+1],Bd[ch0+1]) = one float4
    const float4* PairC = ((const float4*)g_pair) + (ch0 >> 1);

    float af0 = g_proj[0][node * HID + ch0]     + bfb[layer * HID + ch0];
    float af1 = g_proj[0][node * HID + ch0 + 1] + bfb[layer * HID + ch0 + 1];
    float as0 = g_proj[1][node * HID + ch0]     + bsb[layer * HID + ch0];
    float as1 = g_proj[1][node * HID + ch0 + 1] + bsb[layer * HID + ch0 + 1];

    int start = g_rowptr[node], end = g_rowptr[node + 1];
    float acc0 = 0.0f, acc1 = 0.0f;

    int i0 = start + par;
    if (i0 < end) {
        // prime: gathers for edges i0 and i0+2 in flight; e-row for i0 loaded.
        // Clamps use the global bound — out-of-range slots hold other nodes'
        // valid src ids / e-rows; their values are never consumed.
        int s0 = g_srcs[i0];
        int s1 = g_srcs[min(i0 + 2, N_EDGES - 1)];
        float4 p0 = PairC[s0 * 64];
        float4 p1 = PairC[s1 * 64];
        const float* ep0 = &g_es[i0 * NUM_G];
        float4 e0 = *(const float4*)&ep0[0];
        float4 e1 = *(const float4*)&ep0[4];
        float4 e2 = *(const float4*)&ep0[8];
        float4 e3 = *(const float4*)&ep0[12];

        for (int i = i0; i < end; i += 2) {
            // prefetch gather for edge i+4
            int s2 = g_srcs[min(i + 4, N_EDGES - 1)];
            float4 pn = PairC[s2 * 64];
            // prefetch e-row for edge i+2 (consumed next iteration)
            const float* np = &g_es[min(i + 2, N_EDGES - 1) * NUM_G];
            float4 n0 = *(const float4*)&np[0];
            float4 n1 = *(const float4*)&np[4];
            float4 n2 = *(const float4*)&np[8];
            float4 n3 = *(const float4*)&np[12];

            // compute edge i (e-row and gather both issued last iteration)
            float zf0 = af0 + p0.x, zs0 = as0 + p0.y;
            float zf1 = af1 + p0.z, zs1 = as1 + p0.w;
#define RBF1(ev, k)                                       \
            zf0 = fmaf(ev, wf[k].x, zf0);                 \
            zs0 = fmaf(ev, ws[k].x, zs0);                 \
            zf1 = fmaf(ev, wf[k].y, zf1);                 \
            zs1 = fmaf(ev, ws[k].y, zs1);
            RBF1(e0.x, 0)  RBF1(e0.y, 1)  RBF1(e0.z, 2)  RBF1(e0.w, 3)
            RBF1(e1.x, 4)  RBF1(e1.y, 5)  RBF1(e1.z, 6)  RBF1(e1.w, 7)
            RBF1(e2.x, 8)  RBF1(e2.y, 9)  RBF1(e2.z, 10) RBF1(e2.w, 11)
            RBF1(e3.x, 12) RBF1(e3.y, 13) RBF1(e3.z, 14) RBF1(e3.w, 15)
#undef RBF1
            acc0 += sigm(zf0) * softp(zs0);
            acc1 += sigm(zf1) * softp(zs1);

            // rotate pipelines
            p0 = p1; p1 = pn;
            e0 = n0; e1 = n1; e2 = n2; e3 = n3;
        }
    }

    // cross-parity reduction (one barrier per node)
    *(float2*)&sred[par][ch0] = make_float2(acc0, acc1);
    __syncthreads();
    {
        float a = sred[0][tid] + sred[1][tid];
        g_agg[node * HID + tid] = a;
        atomicAdd(&g_sum[tid], a);
        atomicAdd(&g_sq[tid], a * a);
    }
}

// ------------------------- BN + residual + LN + ReLU + residual --------------
__global__ __launch_bounds__(256) void bn_ln_kernel(
    const float* __restrict__ bn_g, const float* __restrict__ bn_b,
    const float* __restrict__ ln_g, const float* __restrict__ ln_b, int layer) {
    __shared__ __align__(16) float sA[HID];
    __shared__ __align__(16) float sB[HID];
    int tid = threadIdx.x;
    if (tid < HID) {
        const float inv = 1.0f / (float)N_NODES;
        float mu = g_sum[tid] * inv;
        float var = g_sq[tid] * inv - mu * mu;
        float rs = rsqrtf(var + 1e-5f);
        float a = rs * bn_g[layer * HID + tid];
        sA[tid] = a;
        sB[tid] = bn_b[layer * HID + tid] - mu * a;
    }
    __syncthreads();

    int warp = tid >> 5, lane = tid & 31;
    int node = blockIdx.x * 8 + warp;
    int ch0 = lane * 4;

    float4 ag = *(const float4*)&g_agg[node * HID + ch0];
    float4 h4 = *(const float4*)&g_h[node * HID + ch0];
    float4 a4 = *(const float4*)&sA[ch0];
    float4 b4 = *(const float4*)&sB[ch0];

    float c0 = fmaf(ag.x, a4.x, b4.x) + h4.x;
    float c1 = fmaf(ag.y, a4.y, b4.y) + h4.y;
    float c2 = fmaf(ag.z, a4.z, b4.z) + h4.z;
    float c3 = fmaf(ag.w, a4.w, b4.w) + h4.w;

    float s = warp_sum(c0 + c1 + c2 + c3);
    float mean = s * (1.0f / HID);
    float sq = warp_sum(c0 * c0 + c1 * c1 + c2 * c2 + c3 * c3);
    float var = sq * (1.0f / HID) - mean * mean;
    float rs = rsqrtf(var + 1e-5f);

    float4 lg = *(const float4*)&ln_g[layer * HID + ch0];
    float4 lb = *(const float4*)&ln_b[layer * HID + ch0];

    float r0 = fmaxf(fmaf((c0 - mean) * rs, lg.x, lb.x), 0.0f) + h4.x;
    float r1 = fmaxf(fmaf((c1 - mean) * rs, lg.y, lb.y), 0.0f) + h4.y;
    float r2 = fmaxf(fmaf((c2 - mean) * rs, lg.z, lb.z), 0.0f) + h4.z;
    float r3 = fmaxf(fmaf((c3 - mean) * rs, lg.w, lb.w), 0.0f) + h4.w;

    *(float4*)&g_h[node * HID + ch0] = make_float4(r0, r1, r2, r3);
}

// ------------------------- final LN + FC -------------------------------------
__global__ __launch_bounds__(256) void final_kernel(
    const float* __restrict__ lng, const float* __restrict__ lnb,
    const float* __restrict__ Wfc, const float* __restrict__ bfc,
    float* __restrict__ out) {
    int warp = threadIdx.x >> 5, lane = threadIdx.x & 31;
    int node = blockIdx.x * 8 + warp;
    int ch0 = lane * 4;

    float4 h4 = *(const float4*)&g_h[node * HID + ch0];
    float s = warp_sum(h4.x + h4.y + h4.z + h4.w);
    float mean = s * (1.0f / HID);
    float sq = warp_sum(h4.x * h4.x + h4.y * h4.y + h4.z * h4.z + h4.w * h4.w);
    float var = sq * (1.0f / HID) - mean * mean;
    float rs = rsqrtf(var + 1e-5f);

    float4 lg = *(const float4*)&lng[ch0];
    float4 lb = *(const float4*)&lnb[ch0];
    float hn0 = fmaf((h4.x - mean) * rs, lg.x, lb.x);
    float hn1 = fmaf((h4.y - mean) * rs, lg.y, lb.y);
    float hn2 = fmaf((h4.z - mean) * rs, lg.z, lb.z);
    float hn3 = fmaf((h4.w - mean) * rs, lg.w, lb.w);

#pragma unroll
    for (int j = 0; j < N_CLS; j++) {
        float p = hn0 * Wfc[(ch0 + 0) * N_CLS + j]
                + hn1 * Wfc[(ch0 + 1) * N_CLS + j]
                + hn2 * Wfc[(ch0 + 2) * N_CLS + j]
                + hn3 * Wfc[(ch0 + 3) * N_CLS + j];
        p = warp_sum(p);
        if (lane == 0) out[node * N_CLS + j] = p + bfc[j];
    }
}

// ------------------------- launch -------------------------------------------
extern "C" void kernel_launch(void* const* d_in, const int* in_sizes, int n_in,
                              void* d_out, int out_size) {
    const float* x        = (const float*)d_in[0];
    const int*   ei       = (const int*)d_in[1];
    const float* dist     = (const float*)d_in[2];
    const float* W_node   = (const float*)d_in[3];
    const float* b_node   = (const float*)d_in[4];
    const float* Wf       = (const float*)d_in[5];
    const float* bf       = (const float*)d_in[6];
    const float* Ws       = (const float*)d_in[7];
    const float* bs       = (const float*)d_in[8];
    const float* bn_g     = (const float*)d_in[9];
    const float* bn_b     = (const float*)d_in[10];
    const float* ln_g     = (const float*)d_in[11];
    const float* ln_b     = (const float*)d_in[12];
    const float* lnout_g  = (const float*)d_in[13];
    const float* lnout_b  = (const float*)d_in[14];
    const float* W_fc     = (const float*)d_in[15];
    const float* b_fc     = (const float*)d_in[16];
    float* out = (float*)d_out;

    setup_kernel<<<(N_NODES * HID + 255) / 256, 256>>>(x, W_node, b_node);   // 1
    count_kernel<<<(N_EDGES + 255) / 256, 256>>>(ei);                        // 2
    scan_kernel<<<1, 1024>>>();                                              // 3
    gemm_node_kernel<<<dim3(313, 4), 256>>>(Wf, Ws, 0);                      // 4
    rbf_scatter_kernel<<<(N_EDGES + 255) / 256, 256>>>(dist, ei);            // 5
    edge_agg_kernel<<<N_NODES, 128>>>(Wf, Ws, bf, bs, 0);                    // 6
    bn_ln_kernel<<<N_NODES / 8, 256>>>(bn_g, bn_b, ln_g, ln_b, 0);           // 7

    for (int l = 1; l < N_LAYERS; l++) {
        gemm_node_kernel<<<dim3(313, 4), 256>>>(Wf, Ws, l);
        edge_agg_kernel<<<N_NODES, 128>>>(Wf, Ws, bf, bs, l);
        bn_ln_kernel<<<N_NODES / 8, 256>>>(bn_g, bn_b, ln_g, ln_b, l);
    }

    final_kernel<<<N_NODES / 8, 256>>>(lnout_g, lnout_b, W_fc, b_fc, out);
}